// round 1
// baseline (speedup 1.0000x reference)
#include <cuda_runtime.h>
#include <math.h>

// Problem constants
#define Bb   2
#define Tt   2048
#define Cc   1024
#define Hh   16
#define DHd  64
#define Mrows (Bb * Tt)          // 4096
#define QKV_N (3 * Cc)           // 3072
#define FFN_N (4 * Cc)           // 4096
#define ATT_SCALE 0.03125f       // C^-0.5 = 1/32
#define LN_EPS 1e-5f

// ---------------------------------------------------------------------------
// Scratch (static device allocations; no cudaMalloc allowed)
// ---------------------------------------------------------------------------
__device__ float g_x1  [Mrows * Cc];        // LN1 output
__device__ float g_qkv [Mrows * QKV_N];     // fused qkv activations [M, 3072]
__device__ float g_attn[Mrows * Cc];        // attention output, concat layout
__device__ float g_y   [Mrows * Cc];        // x + attn proj
__device__ float g_x2  [Mrows * Cc];        // LN2 output
__device__ float g_h   [Mrows * FFN_N];     // FFN hidden
__device__ float g_wqkv[Cc * QKV_N];        // packed [C, 3C] qkv weight

// ---------------------------------------------------------------------------
// Pack Wq/Wk/Wv [H,C,DH] -> g_wqkv [C, 3*C], col n: (sel, h, d)
// ---------------------------------------------------------------------------
__global__ void pack_qkv_kernel(const float* __restrict__ Wq,
                                const float* __restrict__ Wk,
                                const float* __restrict__ Wv) {
    int idx = blockIdx.x * blockDim.x + threadIdx.x;
    if (idx >= Cc * QKV_N) return;
    int c = idx / QKV_N;
    int n = idx - c * QKV_N;
    int sel = n >> 10;        // 0..2
    int m = n & 1023;
    int h = m >> 6;
    int d = m & 63;
    const float* W = (sel == 0) ? Wq : (sel == 1) ? Wk : Wv;
    g_wqkv[idx] = W[(h * Cc + c) * DHd + d];
}

// ---------------------------------------------------------------------------
// LayerNorm over axis 1 (TIME), unbiased variance (ddof=1).
// grid (C/32, B), block (32, 8). Coalesced: consecutive tx -> consecutive c.
// ---------------------------------------------------------------------------
__global__ __launch_bounds__(256)
void ln_axis1_kernel(const float* __restrict__ x,
                     const float* __restrict__ gamma,
                     const float* __restrict__ beta,
                     float* __restrict__ out) {
    int b  = blockIdx.y;
    int tx = threadIdx.x, ty = threadIdx.y;
    int c  = blockIdx.x * 32 + tx;
    const float* xp = x + (size_t)b * Tt * Cc + c;

    float s = 0.f, s2 = 0.f;
    for (int t = ty; t < Tt; t += 8) {
        float v = xp[(size_t)t * Cc];
        s += v; s2 += v * v;
    }
    __shared__ float ss[8][32], sq[8][32], smean[32], srstd[32];
    ss[ty][tx] = s; sq[ty][tx] = s2;
    __syncthreads();
    if (ty == 0) {
        float S = 0.f, S2 = 0.f;
#pragma unroll
        for (int k = 0; k < 8; k++) { S += ss[k][tx]; S2 += sq[k][tx]; }
        float mean = S / (float)Tt;
        float var  = (S2 - (float)Tt * mean * mean) / (float)(Tt - 1);
        smean[tx] = mean;
        srstd[tx] = rsqrtf(var + LN_EPS);
    }
    __syncthreads();
    float mean = smean[tx], rstd = srstd[tx];
    float g = gamma[c], be = beta[c];
    float* op = out + (size_t)b * Tt * Cc + c;
    for (int t = ty; t < Tt; t += 8) {
        op[(size_t)t * Cc] = g * (xp[(size_t)t * Cc] - mean) * rstd + be;
    }
}

// ---------------------------------------------------------------------------
// SGEMM: C[M,N] = epilogue(A[M,K] @ B[K,N]).
// 128x128 block tile, BK=8, 256 threads, 8x8 per-thread microtile.
// M,N multiples of 128; K multiple of 8. Row-major everywhere.
// ---------------------------------------------------------------------------
template<bool BIAS, bool RELU, bool RES>
__global__ __launch_bounds__(256)
void gemm_kernel(const float* __restrict__ A,
                 const float* __restrict__ Bm,
                 const float* __restrict__ bias,
                 const float* __restrict__ res,
                 float* __restrict__ Cout,
                 int M, int N, int K) {
    __shared__ float As[8][128];
    __shared__ float Bs[8][128];

    int tid  = threadIdx.x;
    int row0 = blockIdx.y * 128;
    int col0 = blockIdx.x * 128;
    int tx = tid & 15, ty = tid >> 4;

    int a_r = tid >> 1;           // 0..127
    int a_k = (tid & 1) * 4;      // 0 or 4
    int b_k = tid >> 5;           // 0..7
    int b_c = (tid & 31) * 4;     // 0..124

    const float* Aptr = A  + (size_t)(row0 + a_r) * K + a_k;
    const float* Bptr = Bm + (size_t)b_k * N + col0 + b_c;

    float acc[8][8];
#pragma unroll
    for (int i = 0; i < 8; i++)
#pragma unroll
        for (int j = 0; j < 8; j++) acc[i][j] = 0.f;

    for (int k0 = 0; k0 < K; k0 += 8) {
        float4 av = *(const float4*)(Aptr + k0);
        As[a_k + 0][a_r] = av.x;
        As[a_k + 1][a_r] = av.y;
        As[a_k + 2][a_r] = av.z;
        As[a_k + 3][a_r] = av.w;
        float4 bv = *(const float4*)(Bptr + (size_t)k0 * N);
        *(float4*)&Bs[b_k][b_c] = bv;
        __syncthreads();
#pragma unroll
        for (int kk = 0; kk < 8; kk++) {
            float4 a0 = *(float4*)&As[kk][ty * 8];
            float4 a1 = *(float4*)&As[kk][ty * 8 + 4];
            float4 b0 = *(float4*)&Bs[kk][tx * 8];
            float4 b1 = *(float4*)&Bs[kk][tx * 8 + 4];
            float a[8] = {a0.x, a0.y, a0.z, a0.w, a1.x, a1.y, a1.z, a1.w};
            float bb[8] = {b0.x, b0.y, b0.z, b0.w, b1.x, b1.y, b1.z, b1.w};
#pragma unroll
            for (int i = 0; i < 8; i++)
#pragma unroll
                for (int j = 0; j < 8; j++)
                    acc[i][j] = fmaf(a[i], bb[j], acc[i][j]);
        }
        __syncthreads();
    }

#pragma unroll
    for (int i = 0; i < 8; i++) {
        int r = row0 + ty * 8 + i;
#pragma unroll
        for (int j = 0; j < 8; j += 4) {
            int cI = col0 + tx * 8 + j;
            float4 v = make_float4(acc[i][j], acc[i][j+1], acc[i][j+2], acc[i][j+3]);
            if (BIAS) {
                float4 bi = *(const float4*)&bias[cI];
                v.x += bi.x; v.y += bi.y; v.z += bi.z; v.w += bi.w;
            }
            if (RES) {
                float4 rv = *(const float4*)&res[(size_t)r * N + cI];
                v.x += rv.x; v.y += rv.y; v.z += rv.z; v.w += rv.w;
            }
            if (RELU) {
                v.x = fmaxf(v.x, 0.f); v.y = fmaxf(v.y, 0.f);
                v.z = fmaxf(v.z, 0.f); v.w = fmaxf(v.w, 0.f);
            }
            *(float4*)&Cout[(size_t)r * N + cI] = v;
        }
    }
}

// ---------------------------------------------------------------------------
// Causal flash attention, fp32. BQ=BS=64, DH=64.
// grid (T/64, H, B), 256 threads as (tx=16, ty=16), 4x4 per-thread tiles.
// Q,K stored transposed in smem ([d][row]) so inner loops are LDS.128.
// K buffer is reused for transposed P. Scores scaled by C^-0.5.
// qkv layout: [B*T, 3072] rows; q at col h*64, k at 1024+h*64, v at 2048+h*64.
// Output written directly in concat layout [B*T, 1024].
// ---------------------------------------------------------------------------
#define ATT_PAD 68

__global__ __launch_bounds__(256)
void attn_kernel(const float* __restrict__ qkv, float* __restrict__ outp) {
    extern __shared__ float sh[];
    float* Qt = sh;                       // [64][68]  (d-major)
    float* KP = sh + 64 * ATT_PAD;        // [64][68]  K^T, later P^T
    float* Vs = KP + 64 * ATT_PAD;        // [64][68]  (s-major)

    int qt = blockIdx.x, h = blockIdx.y, b = blockIdx.z;
    int t0 = qt * 64;
    int tid = threadIdx.x;
    int tx = tid & 15, ty = tid >> 4;

    // loader mapping: 4 threads per tile-row, 16 d-elements each
    int lr  = tid & 63;
    int ld0 = (tid >> 6) * 16;

    // Load Q tile (scaled), transposed
    {
        const float* qp = qkv + ((size_t)(b * Tt + t0 + lr)) * QKV_N + h * 64 + ld0;
#pragma unroll
        for (int dd = 0; dd < 16; dd += 4) {
            float4 v = *(const float4*)(qp + dd);
            Qt[(ld0 + dd + 0) * ATT_PAD + lr] = v.x * ATT_SCALE;
            Qt[(ld0 + dd + 1) * ATT_PAD + lr] = v.y * ATT_SCALE;
            Qt[(ld0 + dd + 2) * ATT_PAD + lr] = v.z * ATT_SCALE;
            Qt[(ld0 + dd + 3) * ATT_PAD + lr] = v.w * ATT_SCALE;
        }
    }

    float m[4], l[4], o[4][4];
#pragma unroll
    for (int i = 0; i < 4; i++) {
        m[i] = -1e30f; l[i] = 0.f;
#pragma unroll
        for (int j = 0; j < 4; j++) o[i][j] = 0.f;
    }
    const unsigned FULL = 0xffffffffu;

    for (int s0 = 0; s0 <= t0; s0 += 64) {
        __syncthreads();   // previous P/V reads done; Q visible (first iter)
        // Load K (transposed) and V tiles
        {
            const float* kp = qkv + ((size_t)(b * Tt + s0 + lr)) * QKV_N + Cc + h * 64 + ld0;
#pragma unroll
            for (int dd = 0; dd < 16; dd += 4) {
                float4 v = *(const float4*)(kp + dd);
                KP[(ld0 + dd + 0) * ATT_PAD + lr] = v.x;
                KP[(ld0 + dd + 1) * ATT_PAD + lr] = v.y;
                KP[(ld0 + dd + 2) * ATT_PAD + lr] = v.z;
                KP[(ld0 + dd + 3) * ATT_PAD + lr] = v.w;
            }
            const float* vp = qkv + ((size_t)(b * Tt + s0 + lr)) * QKV_N + 2 * Cc + h * 64 + ld0;
#pragma unroll
            for (int dd = 0; dd < 16; dd += 4) {
                *(float4*)&Vs[lr * ATT_PAD + ld0 + dd] = *(const float4*)(vp + dd);
            }
        }
        __syncthreads();

        // S = Q K^T (4x4 per thread)
        float s[4][4];
#pragma unroll
        for (int i = 0; i < 4; i++)
#pragma unroll
            for (int j = 0; j < 4; j++) s[i][j] = 0.f;
#pragma unroll 8
        for (int kk = 0; kk < 64; kk++) {
            float4 a  = *(float4*)&Qt[kk * ATT_PAD + 4 * ty];
            float4 bb = *(float4*)&KP[kk * ATT_PAD + 4 * tx];
            float av[4] = {a.x, a.y, a.z, a.w};
            float bv[4] = {bb.x, bb.y, bb.z, bb.w};
#pragma unroll
            for (int i = 0; i < 4; i++)
#pragma unroll
                for (int j = 0; j < 4; j++)
                    s[i][j] = fmaf(av[i], bv[j], s[i][j]);
        }

        // causal mask (diagonal block only)
        if (s0 == t0) {
#pragma unroll
            for (int i = 0; i < 4; i++)
#pragma unroll
                for (int j = 0; j < 4; j++)
                    if (4 * tx + j > 4 * ty + i) s[i][j] = -1e30f;
        }

        // online softmax update (row reductions across the 16 tx lanes)
        float corr[4];
#pragma unroll
        for (int i = 0; i < 4; i++) {
            float mx = fmaxf(fmaxf(s[i][0], s[i][1]), fmaxf(s[i][2], s[i][3]));
#pragma unroll
            for (int off = 8; off >= 1; off >>= 1)
                mx = fmaxf(mx, __shfl_xor_sync(FULL, mx, off));
            float mnew = fmaxf(m[i], mx);
            float ps = 0.f;
#pragma unroll
            for (int j = 0; j < 4; j++) {
                s[i][j] = __expf(s[i][j] - mnew);
                ps += s[i][j];
            }
#pragma unroll
            for (int off = 8; off >= 1; off >>= 1)
                ps += __shfl_xor_sync(FULL, ps, off);
            float c = __expf(m[i] - mnew);
            l[i] = l[i] * c + ps;
            m[i] = mnew;
            corr[i] = c;
        }

        __syncthreads();   // all K reads done before P overwrites KP
#pragma unroll
        for (int i = 0; i < 4; i++)
#pragma unroll
            for (int j = 0; j < 4; j++)
                KP[(4 * tx + j) * ATT_PAD + 4 * ty + i] = s[i][j];
#pragma unroll
        for (int i = 0; i < 4; i++)
#pragma unroll
            for (int j = 0; j < 4; j++) o[i][j] *= corr[i];
        __syncthreads();

        // O += P @ V
#pragma unroll 8
        for (int sc = 0; sc < 64; sc++) {
            float4 a  = *(float4*)&KP[sc * ATT_PAD + 4 * ty];
            float4 vv = *(float4*)&Vs[sc * ATT_PAD + 4 * tx];
            float av[4] = {a.x, a.y, a.z, a.w};
            float bv[4] = {vv.x, vv.y, vv.z, vv.w};
#pragma unroll
            for (int i = 0; i < 4; i++)
#pragma unroll
                for (int j = 0; j < 4; j++)
                    o[i][j] = fmaf(av[i], bv[j], o[i][j]);
        }
    }

    // write normalized output in concat layout [B*T, H*DH]
#pragma unroll
    for (int i = 0; i < 4; i++) {
        float inv = 1.f / l[i];
        int r = t0 + 4 * ty + i;
        float* op = outp + ((size_t)(b * Tt + r)) * Cc + h * 64 + 4 * tx;
#pragma unroll
        for (int j = 0; j < 4; j++) op[j] = o[i][j] * inv;
    }
}

// ---------------------------------------------------------------------------
// Launch
// ---------------------------------------------------------------------------
extern "C" void kernel_launch(void* const* d_in, const int* in_sizes, int n_in,
                              void* d_out, int out_size) {
    const float* x      = (const float*)d_in[0];
    const float* Wq     = (const float*)d_in[1];
    const float* Wk     = (const float*)d_in[2];
    const float* Wv     = (const float*)d_in[3];
    const float* Wo     = (const float*)d_in[4];
    const float* bo     = (const float*)d_in[5];
    const float* W1     = (const float*)d_in[6];
    const float* b1     = (const float*)d_in[7];
    const float* W2     = (const float*)d_in[8];
    const float* b2     = (const float*)d_in[9];
    const float* gamma1 = (const float*)d_in[10];
    const float* beta1  = (const float*)d_in[11];
    const float* gamma2 = (const float*)d_in[12];
    const float* beta2  = (const float*)d_in[13];
    float* out = (float*)d_out;

    float *p_x1, *p_qkv, *p_attn, *p_y, *p_x2, *p_h, *p_wqkv;
    cudaGetSymbolAddress((void**)&p_x1,   g_x1);
    cudaGetSymbolAddress((void**)&p_qkv,  g_qkv);
    cudaGetSymbolAddress((void**)&p_attn, g_attn);
    cudaGetSymbolAddress((void**)&p_y,    g_y);
    cudaGetSymbolAddress((void**)&p_x2,   g_x2);
    cudaGetSymbolAddress((void**)&p_h,    g_h);
    cudaGetSymbolAddress((void**)&p_wqkv, g_wqkv);

    // 0) pack qkv weights [H,C,DH]x3 -> [C, 3C]
    pack_qkv_kernel<<<(Cc * QKV_N + 255) / 256, 256>>>(Wq, Wk, Wv);

    // 1) LN1 over time axis
    {
        dim3 grid(Cc / 32, Bb), block(32, 8);
        ln_axis1_kernel<<<grid, block>>>(x, gamma1, beta1, p_x1);
    }

    // 2) fused QKV GEMM: [4096,1024] @ [1024,3072]
    {
        dim3 grid(QKV_N / 128, Mrows / 128);
        gemm_kernel<false, false, false><<<grid, 256>>>(
            p_x1, p_wqkv, nullptr, nullptr, p_qkv, Mrows, QKV_N, Cc);
    }

    // 3) causal flash attention
    {
        int smem = 3 * 64 * ATT_PAD * (int)sizeof(float);
        cudaFuncSetAttribute(attn_kernel,
                             cudaFuncAttributeMaxDynamicSharedMemorySize, smem);
        dim3 grid(Tt / 64, Hh, Bb);
        attn_kernel<<<grid, 256, smem>>>(p_qkv, p_attn);
    }

    // 4) output projection + bias + residual: y = x + attn @ Wo + bo
    {
        dim3 grid(Cc / 128, Mrows / 128);
        gemm_kernel<true, false, true><<<grid, 256>>>(
            p_attn, Wo, bo, x, p_y, Mrows, Cc, Cc);
    }

    // 5) LN2
    {
        dim3 grid(Cc / 32, Bb), block(32, 8);
        ln_axis1_kernel<<<grid, block>>>(p_y, gamma2, beta2, p_x2);
    }

    // 6) FFN1: h = relu(x2 @ W1 + b1)
    {
        dim3 grid(FFN_N / 128, Mrows / 128);
        gemm_kernel<true, true, false><<<grid, 256>>>(
            p_x2, W1, b1, nullptr, p_h, Mrows, FFN_N, Cc);
    }

    // 7) FFN2: out = y + h @ W2 + b2
    {
        dim3 grid(Cc / 128, Mrows / 128);
        gemm_kernel<true, false, true><<<grid, 256>>>(
            p_h, W2, b2, p_y, out, Mrows, Cc, FFN_N);
    }
}

// round 2
// speedup vs baseline: 2.0831x; 2.0831x over previous
#include <cuda_runtime.h>
#include <math.h>
#include <stdint.h>

// Problem constants
#define Bb   2
#define Tt   2048
#define Cc   1024
#define Hh   16
#define DHd  64
#define Mrows (Bb * Tt)          // 4096
#define QKV_N (3 * Cc)           // 3072
#define FFN_N (4 * Cc)           // 4096
#define ATT_SCALE 0.03125f       // C^-0.5 = 1/32
#define LN_EPS 1e-5f

// ---------------------------------------------------------------------------
// Scratch (static device allocations; no cudaMalloc allowed)
// ---------------------------------------------------------------------------
__device__ float g_x1  [Mrows * Cc];        // LN1 output (tf32-rounded)
__device__ float g_qkv [Mrows * QKV_N];     // fused qkv activations
__device__ float g_attn[Mrows * Cc];        // attention output (tf32-rounded)
__device__ float g_y   [Mrows * Cc];        // x + attn proj
__device__ float g_x2  [Mrows * Cc];        // LN2 output (tf32-rounded)
__device__ float g_h   [Mrows * FFN_N];     // FFN hidden (tf32-rounded)
__device__ float g_wqkv[Cc * QKV_N];        // packed [C, 3C] qkv weight (tf32)
__device__ float g_wo  [Cc * Cc];           // tf32-rounded Wo
__device__ float g_w1  [Cc * FFN_N];        // tf32-rounded W1
__device__ float g_w2  [FFN_N * Cc];        // tf32-rounded W2

// ---------------------------------------------------------------------------
// Helpers
// ---------------------------------------------------------------------------
__device__ __forceinline__ float tf32r(float x) {
    uint32_t u;
    asm("cvt.rna.tf32.f32 %0, %1;" : "=r"(u) : "f"(x));
    return __uint_as_float(u);
}

__device__ __forceinline__ void cp_async16(void* smem, const void* gmem) {
    unsigned saddr = (unsigned)__cvta_generic_to_shared(smem);
    asm volatile("cp.async.cg.shared.global [%0], [%1], 16;\n"
                 :: "r"(saddr), "l"(gmem));
}
__device__ __forceinline__ void cp_async_commit() {
    asm volatile("cp.async.commit_group;\n" ::: "memory");
}
__device__ __forceinline__ void cp_async_wait0() {
    asm volatile("cp.async.wait_group 0;\n" ::: "memory");
}

__device__ __forceinline__ void mma_tf32(float c[4],
                                         const uint32_t a[4],
                                         const uint32_t b[2]) {
    asm volatile(
        "mma.sync.aligned.m16n8k8.row.col.f32.tf32.tf32.f32 "
        "{%0,%1,%2,%3}, {%4,%5,%6,%7}, {%8,%9}, {%0,%1,%2,%3};\n"
        : "+f"(c[0]), "+f"(c[1]), "+f"(c[2]), "+f"(c[3])
        : "r"(a[0]), "r"(a[1]), "r"(a[2]), "r"(a[3]),
          "r"(b[0]), "r"(b[1]));
}

// ---------------------------------------------------------------------------
// Pack Wq/Wk/Wv [H,C,DH] -> g_wqkv [C, 3*C] (tf32-rounded)
// ---------------------------------------------------------------------------
__global__ void pack_qkv_kernel(const float* __restrict__ Wq,
                                const float* __restrict__ Wk,
                                const float* __restrict__ Wv) {
    int idx = blockIdx.x * blockDim.x + threadIdx.x;
    if (idx >= Cc * QKV_N) return;
    int c = idx / QKV_N;
    int n = idx - c * QKV_N;
    int sel = n >> 10;
    int m = n & 1023;
    int h = m >> 6;
    int d = m & 63;
    const float* W = (sel == 0) ? Wq : (sel == 1) ? Wk : Wv;
    g_wqkv[idx] = tf32r(W[(h * Cc + c) * DHd + d]);
}

// Round an array to tf32 (for weight matrices)
__global__ void round_kernel(const float* __restrict__ src,
                             float* __restrict__ dst, int n) {
    int i = blockIdx.x * blockDim.x + threadIdx.x;
    if (i < n) dst[i] = tf32r(src[i]);
}

// ---------------------------------------------------------------------------
// LayerNorm over axis 1 (TIME), unbiased variance. Output tf32-rounded.
// ---------------------------------------------------------------------------
__global__ __launch_bounds__(256)
void ln_axis1_kernel(const float* __restrict__ x,
                     const float* __restrict__ gamma,
                     const float* __restrict__ beta,
                     float* __restrict__ out) {
    int b  = blockIdx.y;
    int tx = threadIdx.x, ty = threadIdx.y;
    int c  = blockIdx.x * 32 + tx;
    const float* xp = x + (size_t)b * Tt * Cc + c;

    float s = 0.f, s2 = 0.f;
    for (int t = ty; t < Tt; t += 8) {
        float v = xp[(size_t)t * Cc];
        s += v; s2 += v * v;
    }
    __shared__ float ss[8][32], sq[8][32], smean[32], srstd[32];
    ss[ty][tx] = s; sq[ty][tx] = s2;
    __syncthreads();
    if (ty == 0) {
        float S = 0.f, S2 = 0.f;
#pragma unroll
        for (int k = 0; k < 8; k++) { S += ss[k][tx]; S2 += sq[k][tx]; }
        float mean = S / (float)Tt;
        float var  = (S2 - (float)Tt * mean * mean) / (float)(Tt - 1);
        smean[tx] = mean;
        srstd[tx] = rsqrtf(var + LN_EPS);
    }
    __syncthreads();
    float mean = smean[tx], rstd = srstd[tx];
    float g = gamma[c], be = beta[c];
    float* op = out + (size_t)b * Tt * Cc + c;
    for (int t = ty; t < Tt; t += 8) {
        op[(size_t)t * Cc] = tf32r(g * (xp[(size_t)t * Cc] - mean) * rstd + be);
    }
}

// ---------------------------------------------------------------------------
// TF32 tensor-core GEMM: C[M,N] = epilogue(A[M,K] @ B[K,N]).
// Inputs must be pre-rounded to tf32 (rna). 128x128 block tile, BK=16,
// 256 threads = 8 warps (4x2), warp tile 32x64, mma.m16n8k8.
// cp.async double-buffered. M%128==0, N%128==0, K%16==0.
// ---------------------------------------------------------------------------
template<bool BIAS, bool RELU, bool RES, bool ROUND_OUT>
__global__ __launch_bounds__(256, 2)
void gemm_tf32_kernel(const float* __restrict__ A,
                      const float* __restrict__ Bm,
                      const float* __restrict__ bias,
                      const float* __restrict__ res,
                      float* __restrict__ Cout,
                      int M, int N, int K) {
    __shared__ float As[2][128][20];    // [m][k], stride 20 -> conflict-free frags
    __shared__ float Bs[2][16][136];    // [k][n], stride 136 -> conflict-free frags

    const int tid  = threadIdx.x;
    const int lane = tid & 31;
    const int warp = tid >> 5;
    const int wm   = warp >> 1;         // 0..3
    const int wn   = warp & 1;          // 0..1
    const int gid  = lane >> 2;         // 0..7
    const int tid4 = lane & 3;          // 0..3

    const int row0 = blockIdx.y * 128;
    const int col0 = blockIdx.x * 128;

    // global load mapping
    const int arow = tid >> 1;                 // with r offset below
    const int nIter = K >> 4;

    float acc[2][8][4];
#pragma unroll
    for (int i = 0; i < 2; i++)
#pragma unroll
        for (int j = 0; j < 8; j++)
#pragma unroll
            for (int q = 0; q < 4; q++) acc[i][j][q] = 0.f;

    // prefetch tile 0 into buffer 0
    {
        const int k0 = 0;
#pragma unroll
        for (int r = 0; r < 2; r++) {
            int id = tid + 256 * r;
            int ar = id >> 2, ac = (id & 3) << 2;
            cp_async16(&As[0][ar][ac], A + (size_t)(row0 + ar) * K + k0 + ac);
        }
#pragma unroll
        for (int r = 0; r < 2; r++) {
            int id = tid + 256 * r;
            int br = id >> 5, bc = (id & 31) << 2;
            cp_async16(&Bs[0][br][bc], Bm + (size_t)(k0 + br) * N + col0 + bc);
        }
        cp_async_commit();
    }

    for (int it = 0; it < nIter; ++it) {
        const int buf = it & 1;
        cp_async_wait0();
        __syncthreads();

        if (it + 1 < nIter) {
            const int k0 = (it + 1) << 4;
            const int nb = buf ^ 1;
#pragma unroll
            for (int r = 0; r < 2; r++) {
                int id = tid + 256 * r;
                int ar = id >> 2, ac = (id & 3) << 2;
                cp_async16(&As[nb][ar][ac], A + (size_t)(row0 + ar) * K + k0 + ac);
            }
#pragma unroll
            for (int r = 0; r < 2; r++) {
                int id = tid + 256 * r;
                int br = id >> 5, bc = (id & 31) << 2;
                cp_async16(&Bs[nb][br][bc], Bm + (size_t)(k0 + br) * N + col0 + bc);
            }
            cp_async_commit();
        }

#pragma unroll
        for (int ks = 0; ks < 2; ks++) {
            const int k0s = ks * 8;
            uint32_t af[2][4];
#pragma unroll
            for (int i = 0; i < 2; i++) {
                int rbase = wm * 32 + i * 16 + gid;
                af[i][0] = __float_as_uint(As[buf][rbase    ][k0s + tid4]);
                af[i][1] = __float_as_uint(As[buf][rbase + 8][k0s + tid4]);
                af[i][2] = __float_as_uint(As[buf][rbase    ][k0s + tid4 + 4]);
                af[i][3] = __float_as_uint(As[buf][rbase + 8][k0s + tid4 + 4]);
            }
            uint32_t bf[8][2];
#pragma unroll
            for (int j = 0; j < 8; j++) {
                int nbv = wn * 64 + j * 8 + gid;
                bf[j][0] = __float_as_uint(Bs[buf][k0s + tid4    ][nbv]);
                bf[j][1] = __float_as_uint(Bs[buf][k0s + tid4 + 4][nbv]);
            }
#pragma unroll
            for (int i = 0; i < 2; i++)
#pragma unroll
                for (int j = 0; j < 8; j++)
                    mma_tf32(acc[i][j], af[i], bf[j]);
        }
    }
    __syncthreads();

    // epilogue
#pragma unroll
    for (int i = 0; i < 2; i++) {
#pragma unroll
        for (int hr = 0; hr < 2; hr++) {
            int r = row0 + wm * 32 + i * 16 + gid + hr * 8;
#pragma unroll
            for (int j = 0; j < 8; j++) {
                int cI = col0 + wn * 64 + j * 8 + 2 * tid4;
                float v0 = acc[i][j][hr * 2];
                float v1 = acc[i][j][hr * 2 + 1];
                if (BIAS) {
                    float2 bi = *(const float2*)&bias[cI];
                    v0 += bi.x; v1 += bi.y;
                }
                if (RES) {
                    float2 rv = *(const float2*)&res[(size_t)r * N + cI];
                    v0 += rv.x; v1 += rv.y;
                }
                if (RELU) { v0 = fmaxf(v0, 0.f); v1 = fmaxf(v1, 0.f); }
                if (ROUND_OUT) { v0 = tf32r(v0); v1 = tf32r(v1); }
                float2 o = make_float2(v0, v1);
                *(float2*)&Cout[(size_t)r * N + cI] = o;
            }
        }
    }
}

// ---------------------------------------------------------------------------
// Causal flash attention, fp32 (unchanged except tf32-rounded output).
// ---------------------------------------------------------------------------
#define ATT_PAD 68

__global__ __launch_bounds__(256)
void attn_kernel(const float* __restrict__ qkv, float* __restrict__ outp) {
    extern __shared__ float sh[];
    float* Qt = sh;                       // [64][68]  (d-major)
    float* KP = sh + 64 * ATT_PAD;        // [64][68]  K^T, later P^T
    float* Vs = KP + 64 * ATT_PAD;        // [64][68]  (s-major)

    int qt = blockIdx.x, h = blockIdx.y, b = blockIdx.z;
    int t0 = qt * 64;
    int tid = threadIdx.x;
    int tx = tid & 15, ty = tid >> 4;

    int lr  = tid & 63;
    int ld0 = (tid >> 6) * 16;

    {
        const float* qp = qkv + ((size_t)(b * Tt + t0 + lr)) * QKV_N + h * 64 + ld0;
#pragma unroll
        for (int dd = 0; dd < 16; dd += 4) {
            float4 v = *(const float4*)(qp + dd);
            Qt[(ld0 + dd + 0) * ATT_PAD + lr] = v.x * ATT_SCALE;
            Qt[(ld0 + dd + 1) * ATT_PAD + lr] = v.y * ATT_SCALE;
            Qt[(ld0 + dd + 2) * ATT_PAD + lr] = v.z * ATT_SCALE;
            Qt[(ld0 + dd + 3) * ATT_PAD + lr] = v.w * ATT_SCALE;
        }
    }

    float m[4], l[4], o[4][4];
#pragma unroll
    for (int i = 0; i < 4; i++) {
        m[i] = -1e30f; l[i] = 0.f;
#pragma unroll
        for (int j = 0; j < 4; j++) o[i][j] = 0.f;
    }
    const unsigned FULL = 0xffffffffu;

    for (int s0 = 0; s0 <= t0; s0 += 64) {
        __syncthreads();
        {
            const float* kp = qkv + ((size_t)(b * Tt + s0 + lr)) * QKV_N + Cc + h * 64 + ld0;
#pragma unroll
            for (int dd = 0; dd < 16; dd += 4) {
                float4 v = *(const float4*)(kp + dd);
                KP[(ld0 + dd + 0) * ATT_PAD + lr] = v.x;
                KP[(ld0 + dd + 1) * ATT_PAD + lr] = v.y;
                KP[(ld0 + dd + 2) * ATT_PAD + lr] = v.z;
                KP[(ld0 + dd + 3) * ATT_PAD + lr] = v.w;
            }
            const float* vp = qkv + ((size_t)(b * Tt + s0 + lr)) * QKV_N + 2 * Cc + h * 64 + ld0;
#pragma unroll
            for (int dd = 0; dd < 16; dd += 4) {
                *(float4*)&Vs[lr * ATT_PAD + ld0 + dd] = *(const float4*)(vp + dd);
            }
        }
        __syncthreads();

        float s[4][4];
#pragma unroll
        for (int i = 0; i < 4; i++)
#pragma unroll
            for (int j = 0; j < 4; j++) s[i][j] = 0.f;
#pragma unroll 8
        for (int kk = 0; kk < 64; kk++) {
            float4 a  = *(float4*)&Qt[kk * ATT_PAD + 4 * ty];
            float4 bb = *(float4*)&KP[kk * ATT_PAD + 4 * tx];
            float av[4] = {a.x, a.y, a.z, a.w};
            float bv[4] = {bb.x, bb.y, bb.z, bb.w};
#pragma unroll
            for (int i = 0; i < 4; i++)
#pragma unroll
                for (int j = 0; j < 4; j++)
                    s[i][j] = fmaf(av[i], bv[j], s[i][j]);
        }

        if (s0 == t0) {
#pragma unroll
            for (int i = 0; i < 4; i++)
#pragma unroll
                for (int j = 0; j < 4; j++)
                    if (4 * tx + j > 4 * ty + i) s[i][j] = -1e30f;
        }

        float corr[4];
#pragma unroll
        for (int i = 0; i < 4; i++) {
            float mx = fmaxf(fmaxf(s[i][0], s[i][1]), fmaxf(s[i][2], s[i][3]));
#pragma unroll
            for (int off = 8; off >= 1; off >>= 1)
                mx = fmaxf(mx, __shfl_xor_sync(FULL, mx, off));
            float mnew = fmaxf(m[i], mx);
            float ps = 0.f;
#pragma unroll
            for (int j = 0; j < 4; j++) {
                s[i][j] = __expf(s[i][j] - mnew);
                ps += s[i][j];
            }
#pragma unroll
            for (int off = 8; off >= 1; off >>= 1)
                ps += __shfl_xor_sync(FULL, ps, off);
            float c = __expf(m[i] - mnew);
            l[i] = l[i] * c + ps;
            m[i] = mnew;
            corr[i] = c;
        }

        __syncthreads();
#pragma unroll
        for (int i = 0; i < 4; i++)
#pragma unroll
            for (int j = 0; j < 4; j++)
                KP[(4 * tx + j) * ATT_PAD + 4 * ty + i] = s[i][j];
#pragma unroll
        for (int i = 0; i < 4; i++)
#pragma unroll
            for (int j = 0; j < 4; j++) o[i][j] *= corr[i];
        __syncthreads();

#pragma unroll 8
        for (int sc = 0; sc < 64; sc++) {
            float4 a  = *(float4*)&KP[sc * ATT_PAD + 4 * ty];
            float4 vv = *(float4*)&Vs[sc * ATT_PAD + 4 * tx];
            float av[4] = {a.x, a.y, a.z, a.w};
            float bv[4] = {vv.x, vv.y, vv.z, vv.w};
#pragma unroll
            for (int i = 0; i < 4; i++)
#pragma unroll
                for (int j = 0; j < 4; j++)
                    o[i][j] = fmaf(av[i], bv[j], o[i][j]);
        }
    }

#pragma unroll
    for (int i = 0; i < 4; i++) {
        float inv = 1.f / l[i];
        int r = t0 + 4 * ty + i;
        float* op = outp + ((size_t)(b * Tt + r)) * Cc + h * 64 + 4 * tx;
#pragma unroll
        for (int j = 0; j < 4; j++) op[j] = tf32r(o[i][j] * inv);
    }
}

// ---------------------------------------------------------------------------
// Launch
// ---------------------------------------------------------------------------
extern "C" void kernel_launch(void* const* d_in, const int* in_sizes, int n_in,
                              void* d_out, int out_size) {
    const float* x      = (const float*)d_in[0];
    const float* Wq     = (const float*)d_in[1];
    const float* Wk     = (const float*)d_in[2];
    const float* Wv     = (const float*)d_in[3];
    const float* Wo     = (const float*)d_in[4];
    const float* bo     = (const float*)d_in[5];
    const float* W1     = (const float*)d_in[6];
    const float* b1     = (const float*)d_in[7];
    const float* W2     = (const float*)d_in[8];
    const float* b2     = (const float*)d_in[9];
    const float* gamma1 = (const float*)d_in[10];
    const float* beta1  = (const float*)d_in[11];
    const float* gamma2 = (const float*)d_in[12];
    const float* beta2  = (const float*)d_in[13];
    float* out = (float*)d_out;

    float *p_x1, *p_qkv, *p_attn, *p_y, *p_x2, *p_h, *p_wqkv, *p_wo, *p_w1, *p_w2;
    cudaGetSymbolAddress((void**)&p_x1,   g_x1);
    cudaGetSymbolAddress((void**)&p_qkv,  g_qkv);
    cudaGetSymbolAddress((void**)&p_attn, g_attn);
    cudaGetSymbolAddress((void**)&p_y,    g_y);
    cudaGetSymbolAddress((void**)&p_x2,   g_x2);
    cudaGetSymbolAddress((void**)&p_h,    g_h);
    cudaGetSymbolAddress((void**)&p_wqkv, g_wqkv);
    cudaGetSymbolAddress((void**)&p_wo,   g_wo);
    cudaGetSymbolAddress((void**)&p_w1,   g_w1);
    cudaGetSymbolAddress((void**)&p_w2,   g_w2);

    // 0) pack + round weights
    pack_qkv_kernel<<<(Cc * QKV_N + 255) / 256, 256>>>(Wq, Wk, Wv);
    round_kernel<<<(Cc * Cc + 255) / 256, 256>>>(Wo, p_wo, Cc * Cc);
    round_kernel<<<(Cc * FFN_N + 255) / 256, 256>>>(W1, p_w1, Cc * FFN_N);
    round_kernel<<<(FFN_N * Cc + 255) / 256, 256>>>(W2, p_w2, FFN_N * Cc);

    // 1) LN1 over time axis (tf32-rounded out)
    {
        dim3 grid(Cc / 32, Bb), block(32, 8);
        ln_axis1_kernel<<<grid, block>>>(x, gamma1, beta1, p_x1);
    }

    // 2) fused QKV GEMM (tf32 tensor cores): [4096,1024] @ [1024,3072]
    {
        dim3 grid(QKV_N / 128, Mrows / 128);
        gemm_tf32_kernel<false, false, false, false><<<grid, 256>>>(
            p_x1, p_wqkv, nullptr, nullptr, p_qkv, Mrows, QKV_N, Cc);
    }

    // 3) causal flash attention (fp32, output tf32-rounded)
    {
        int smem = 3 * 64 * ATT_PAD * (int)sizeof(float);
        cudaFuncSetAttribute(attn_kernel,
                             cudaFuncAttributeMaxDynamicSharedMemorySize, smem);
        dim3 grid(Tt / 64, Hh, Bb);
        attn_kernel<<<grid, 256, smem>>>(p_qkv, p_attn);
    }

    // 4) output projection + bias + residual: y = x + attn @ Wo + bo
    {
        dim3 grid(Cc / 128, Mrows / 128);
        gemm_tf32_kernel<true, false, true, false><<<grid, 256>>>(
            p_attn, p_wo, bo, x, p_y, Mrows, Cc, Cc);
    }

    // 5) LN2 (tf32-rounded out)
    {
        dim3 grid(Cc / 32, Bb), block(32, 8);
        ln_axis1_kernel<<<grid, block>>>(p_y, gamma2, beta2, p_x2);
    }

    // 6) FFN1: h = relu(x2 @ W1 + b1), output tf32-rounded
    {
        dim3 grid(FFN_N / 128, Mrows / 128);
        gemm_tf32_kernel<true, true, false, true><<<grid, 256>>>(
            p_x2, p_w1, b1, nullptr, p_h, Mrows, FFN_N, Cc);
    }

    // 7) FFN2: out = y + h @ W2 + b2
    {
        dim3 grid(Cc / 128, Mrows / 128);
        gemm_tf32_kernel<true, false, true, false><<<grid, 256>>>(
            p_h, p_w2, b2, p_y, out, Mrows, Cc, FFN_N);
    }
}

// round 3
// speedup vs baseline: 3.2279x; 1.5496x over previous
#include <cuda_runtime.h>
#include <math.h>
#include <stdint.h>

// Problem constants
#define Bb   2
#define Tt   2048
#define Cc   1024
#define Hh   16
#define DHd  64
#define Mrows (Bb * Tt)          // 4096
#define QKV_N (3 * Cc)           // 3072
#define FFN_N (4 * Cc)           // 4096
#define ATT_SCALE 0.03125f       // C^-0.5 = 1/32
#define LN_EPS 1e-5f

// ---------------------------------------------------------------------------
// Scratch (static device allocations; no cudaMalloc allowed)
// ---------------------------------------------------------------------------
__device__ float g_x1  [Mrows * Cc];
__device__ float g_qkv [Mrows * QKV_N];
__device__ float g_attn[Mrows * Cc];
__device__ float g_y   [Mrows * Cc];
__device__ float g_x2  [Mrows * Cc];
__device__ float g_h   [Mrows * FFN_N];
__device__ float g_wqkv[Cc * QKV_N];
__device__ float g_wo  [Cc * Cc];
__device__ float g_w1  [Cc * FFN_N];
__device__ float g_w2  [FFN_N * Cc];

// ---------------------------------------------------------------------------
// Helpers
// ---------------------------------------------------------------------------
__device__ __forceinline__ float tf32r(float x) {
    uint32_t u;
    asm("cvt.rna.tf32.f32 %0, %1;" : "=r"(u) : "f"(x));
    return __uint_as_float(u);
}

__device__ __forceinline__ void cp_async16(void* smem, const void* gmem) {
    unsigned saddr = (unsigned)__cvta_generic_to_shared(smem);
    asm volatile("cp.async.cg.shared.global [%0], [%1], 16;\n"
                 :: "r"(saddr), "l"(gmem));
}
__device__ __forceinline__ void cp_async_commit() {
    asm volatile("cp.async.commit_group;\n" ::: "memory");
}
__device__ __forceinline__ void cp_async_wait0() {
    asm volatile("cp.async.wait_group 0;\n" ::: "memory");
}

__device__ __forceinline__ void mma_tf32(float c[4],
                                         const uint32_t a[4],
                                         const uint32_t b[2]) {
    asm volatile(
        "mma.sync.aligned.m16n8k8.row.col.f32.tf32.tf32.f32 "
        "{%0,%1,%2,%3}, {%4,%5,%6,%7}, {%8,%9}, {%0,%1,%2,%3};\n"
        : "+f"(c[0]), "+f"(c[1]), "+f"(c[2]), "+f"(c[3])
        : "r"(a[0]), "r"(a[1]), "r"(a[2]), "r"(a[3]),
          "r"(b[0]), "r"(b[1]));
}

// ---------------------------------------------------------------------------
// Pack Wq/Wk/Wv [H,C,DH] -> g_wqkv [C, 3*C] (tf32-rounded)
// ---------------------------------------------------------------------------
__global__ void pack_qkv_kernel(const float* __restrict__ Wq,
                                const float* __restrict__ Wk,
                                const float* __restrict__ Wv) {
    int idx = blockIdx.x * blockDim.x + threadIdx.x;
    if (idx >= Cc * QKV_N) return;
    int c = idx / QKV_N;
    int n = idx - c * QKV_N;
    int sel = n >> 10;
    int m = n & 1023;
    int h = m >> 6;
    int d = m & 63;
    const float* W = (sel == 0) ? Wq : (sel == 1) ? Wk : Wv;
    g_wqkv[idx] = tf32r(W[(h * Cc + c) * DHd + d]);
}

__global__ void round_kernel(const float* __restrict__ src,
                             float* __restrict__ dst, int n) {
    int i = blockIdx.x * blockDim.x + threadIdx.x;
    if (i < n) dst[i] = tf32r(src[i]);
}

// ---------------------------------------------------------------------------
// LayerNorm over axis 1 (TIME), unbiased variance. Output tf32-rounded.
// ---------------------------------------------------------------------------
__global__ __launch_bounds__(256)
void ln_axis1_kernel(const float* __restrict__ x,
                     const float* __restrict__ gamma,
                     const float* __restrict__ beta,
                     float* __restrict__ out) {
    int b  = blockIdx.y;
    int tx = threadIdx.x, ty = threadIdx.y;
    int c  = blockIdx.x * 32 + tx;
    const float* xp = x + (size_t)b * Tt * Cc + c;

    float s = 0.f, s2 = 0.f;
    for (int t = ty; t < Tt; t += 8) {
        float v = xp[(size_t)t * Cc];
        s += v; s2 += v * v;
    }
    __shared__ float ss[8][32], sq[8][32], smean[32], srstd[32];
    ss[ty][tx] = s; sq[ty][tx] = s2;
    __syncthreads();
    if (ty == 0) {
        float S = 0.f, S2 = 0.f;
#pragma unroll
        for (int k = 0; k < 8; k++) { S += ss[k][tx]; S2 += sq[k][tx]; }
        float mean = S / (float)Tt;
        float var  = (S2 - (float)Tt * mean * mean) / (float)(Tt - 1);
        smean[tx] = mean;
        srstd[tx] = rsqrtf(var + LN_EPS);
    }
    __syncthreads();
    float mean = smean[tx], rstd = srstd[tx];
    float g = gamma[c], be = beta[c];
    float* op = out + (size_t)b * Tt * Cc + c;
    for (int t = ty; t < Tt; t += 8) {
        op[(size_t)t * Cc] = tf32r(g * (xp[(size_t)t * Cc] - mean) * rstd + be);
    }
}

// ---------------------------------------------------------------------------
// TF32 tensor-core GEMM (unchanged from Round 2).
// ---------------------------------------------------------------------------
template<bool BIAS, bool RELU, bool RES, bool ROUND_OUT>
__global__ __launch_bounds__(256, 2)
void gemm_tf32_kernel(const float* __restrict__ A,
                      const float* __restrict__ Bm,
                      const float* __restrict__ bias,
                      const float* __restrict__ res,
                      float* __restrict__ Cout,
                      int M, int N, int K) {
    __shared__ float As[2][128][20];
    __shared__ float Bs[2][16][136];

    const int tid  = threadIdx.x;
    const int lane = tid & 31;
    const int warp = tid >> 5;
    const int wm   = warp >> 1;
    const int wn   = warp & 1;
    const int gid  = lane >> 2;
    const int tid4 = lane & 3;

    const int row0 = blockIdx.y * 128;
    const int col0 = blockIdx.x * 128;
    const int nIter = K >> 4;

    float acc[2][8][4];
#pragma unroll
    for (int i = 0; i < 2; i++)
#pragma unroll
        for (int j = 0; j < 8; j++)
#pragma unroll
            for (int q = 0; q < 4; q++) acc[i][j][q] = 0.f;

    {
#pragma unroll
        for (int r = 0; r < 2; r++) {
            int id = tid + 256 * r;
            int ar = id >> 2, ac = (id & 3) << 2;
            cp_async16(&As[0][ar][ac], A + (size_t)(row0 + ar) * K + ac);
        }
#pragma unroll
        for (int r = 0; r < 2; r++) {
            int id = tid + 256 * r;
            int br = id >> 5, bc = (id & 31) << 2;
            cp_async16(&Bs[0][br][bc], Bm + (size_t)br * N + col0 + bc);
        }
        cp_async_commit();
    }

    for (int it = 0; it < nIter; ++it) {
        const int buf = it & 1;
        cp_async_wait0();
        __syncthreads();

        if (it + 1 < nIter) {
            const int k0 = (it + 1) << 4;
            const int nb = buf ^ 1;
#pragma unroll
            for (int r = 0; r < 2; r++) {
                int id = tid + 256 * r;
                int ar = id >> 2, ac = (id & 3) << 2;
                cp_async16(&As[nb][ar][ac], A + (size_t)(row0 + ar) * K + k0 + ac);
            }
#pragma unroll
            for (int r = 0; r < 2; r++) {
                int id = tid + 256 * r;
                int br = id >> 5, bc = (id & 31) << 2;
                cp_async16(&Bs[nb][br][bc], Bm + (size_t)(k0 + br) * N + col0 + bc);
            }
            cp_async_commit();
        }

#pragma unroll
        for (int ks = 0; ks < 2; ks++) {
            const int k0s = ks * 8;
            uint32_t af[2][4];
#pragma unroll
            for (int i = 0; i < 2; i++) {
                int rbase = wm * 32 + i * 16 + gid;
                af[i][0] = __float_as_uint(As[buf][rbase    ][k0s + tid4]);
                af[i][1] = __float_as_uint(As[buf][rbase + 8][k0s + tid4]);
                af[i][2] = __float_as_uint(As[buf][rbase    ][k0s + tid4 + 4]);
                af[i][3] = __float_as_uint(As[buf][rbase + 8][k0s + tid4 + 4]);
            }
            uint32_t bf[8][2];
#pragma unroll
            for (int j = 0; j < 8; j++) {
                int nbv = wn * 64 + j * 8 + gid;
                bf[j][0] = __float_as_uint(Bs[buf][k0s + tid4    ][nbv]);
                bf[j][1] = __float_as_uint(Bs[buf][k0s + tid4 + 4][nbv]);
            }
#pragma unroll
            for (int i = 0; i < 2; i++)
#pragma unroll
                for (int j = 0; j < 8; j++)
                    mma_tf32(acc[i][j], af[i], bf[j]);
        }
    }
    __syncthreads();

#pragma unroll
    for (int i = 0; i < 2; i++) {
#pragma unroll
        for (int hr = 0; hr < 2; hr++) {
            int r = row0 + wm * 32 + i * 16 + gid + hr * 8;
#pragma unroll
            for (int j = 0; j < 8; j++) {
                int cI = col0 + wn * 64 + j * 8 + 2 * tid4;
                float v0 = acc[i][j][hr * 2];
                float v1 = acc[i][j][hr * 2 + 1];
                if (BIAS) {
                    float2 bi = *(const float2*)&bias[cI];
                    v0 += bi.x; v1 += bi.y;
                }
                if (RES) {
                    float2 rv = *(const float2*)&res[(size_t)r * N + cI];
                    v0 += rv.x; v1 += rv.y;
                }
                if (RELU) { v0 = fmaxf(v0, 0.f); v1 = fmaxf(v1, 0.f); }
                if (ROUND_OUT) { v0 = tf32r(v0); v1 = tf32r(v1); }
                float2 o = make_float2(v0, v1);
                *(float2*)&Cout[(size_t)r * N + cI] = o;
            }
        }
    }
}

// ---------------------------------------------------------------------------
// Causal flash attention, tf32 tensor cores.
// BQ=BS=64, DH=64, 128 threads = 4 warps; warp w owns Q rows 16w..16w+15.
// Q fragments register-resident. K/V double-buffered via cp.async.
// P staged (tf32-rounded) through the consumed K buffer.
// Smem strides: K/Q/P 68 floats (banks 4*gid+tid4), V 72 floats (8*tid4+gid).
// ---------------------------------------------------------------------------
#define KSTR 68
#define VSTR 72
#define ATT_SMEM ((64*KSTR + 2*64*KSTR + 2*64*VSTR) * 4)

__global__ __launch_bounds__(128, 2)
void attn_mma_kernel(const float* __restrict__ qkv, float* __restrict__ outp) {
    extern __shared__ float sh[];
    float* Qs = sh;                          // [64][KSTR]
    float* Ks = Qs + 64 * KSTR;              // [2][64][KSTR]
    float* Vs = Ks + 2 * 64 * KSTR;          // [2][64][VSTR]

    const int qt = blockIdx.x, h = blockIdx.y, b = blockIdx.z;
    const int t0 = qt * 64;
    const int tid  = threadIdx.x;
    const int lane = tid & 31;
    const int warp = tid >> 5;
    const int gid  = lane >> 2;
    const int tid4 = lane & 3;
    const unsigned FULL = 0xffffffffu;

    const float* base = qkv + (size_t)(b * Tt) * QKV_N + h * 64;

    // ---- load Q tile (scaled) into smem, coalesced ----
#pragma unroll
    for (int r = 0; r < 8; r++) {
        int id  = tid + 128 * r;         // 0..1023
        int row = id >> 4;
        int qc  = (id & 15) * 4;
        float4 v = *(const float4*)(base + (size_t)(t0 + row) * QKV_N + qc);
        Qs[row * KSTR + qc + 0] = v.x * ATT_SCALE;
        Qs[row * KSTR + qc + 1] = v.y * ATT_SCALE;
        Qs[row * KSTR + qc + 2] = v.z * ATT_SCALE;
        Qs[row * KSTR + qc + 3] = v.w * ATT_SCALE;
    }

    // ---- prefetch K/V tile 0 ----
    {
        const float* kb = base + Cc;
        const float* vb = base + 2 * Cc;
#pragma unroll
        for (int r = 0; r < 8; r++) {
            int id  = tid + 128 * r;
            int row = id >> 4;
            int qc  = (id & 15) * 4;
            cp_async16(&Ks[row * KSTR + qc], kb + (size_t)row * QKV_N + qc);
            cp_async16(&Vs[row * VSTR + qc], vb + (size_t)row * QKV_N + qc);
        }
        cp_async_commit();
    }
    __syncthreads();

    // ---- Q fragments to registers (A-frags, 8 k-steps) ----
    uint32_t qa[8][4];
    {
        int rb = (16 * warp + gid) * KSTR;
#pragma unroll
        for (int k = 0; k < 8; k++) {
            qa[k][0] = __float_as_uint(Qs[rb + 8 * k + tid4]);
            qa[k][1] = __float_as_uint(Qs[rb + 8 * KSTR + 8 * k + tid4]);
            qa[k][2] = __float_as_uint(Qs[rb + 8 * k + tid4 + 4]);
            qa[k][3] = __float_as_uint(Qs[rb + 8 * KSTR + 8 * k + tid4 + 4]);
        }
    }

    float m0 = -1e30f, m1 = -1e30f, l0 = 0.f, l1 = 0.f;
    float o[8][4];
#pragma unroll
    for (int j = 0; j < 8; j++)
#pragma unroll
        for (int q = 0; q < 4; q++) o[j][q] = 0.f;

    const int nt = qt + 1;
    for (int it = 0; it < nt; ++it) {
        const int buf = it & 1;
        float* Kb = Ks + buf * 64 * KSTR;
        float* Vb = Vs + buf * 64 * VSTR;

        cp_async_wait0();
        __syncthreads();

        if (it + 1 < nt) {
            const int s0 = (it + 1) * 64;
            float* Kn = Ks + (buf ^ 1) * 64 * KSTR;
            float* Vn = Vs + (buf ^ 1) * 64 * VSTR;
            const float* kb = base + Cc     + (size_t)s0 * QKV_N;
            const float* vb = base + 2 * Cc + (size_t)s0 * QKV_N;
#pragma unroll
            for (int r = 0; r < 8; r++) {
                int id  = tid + 128 * r;
                int row = id >> 4;
                int qc  = (id & 15) * 4;
                cp_async16(&Kn[row * KSTR + qc], kb + (size_t)row * QKV_N + qc);
                cp_async16(&Vn[row * VSTR + qc], vb + (size_t)row * QKV_N + qc);
            }
            cp_async_commit();
        }

        // ---- S = Q K^T ----
        float sc[8][4];
#pragma unroll
        for (int j = 0; j < 8; j++)
#pragma unroll
            for (int q = 0; q < 4; q++) sc[j][q] = 0.f;
#pragma unroll
        for (int k = 0; k < 8; k++) {
            uint32_t kb2[8][2];
#pragma unroll
            for (int j = 0; j < 8; j++) {
                int rb = (8 * j + gid) * KSTR + 8 * k;
                kb2[j][0] = __float_as_uint(Kb[rb + tid4]);
                kb2[j][1] = __float_as_uint(Kb[rb + tid4 + 4]);
            }
#pragma unroll
            for (int j = 0; j < 8; j++)
                mma_tf32(sc[j], qa[k], kb2[j]);
        }

        // ---- causal mask on diagonal tile ----
        if (it == qt) {
            int r0 = 16 * warp + gid;
#pragma unroll
            for (int j = 0; j < 8; j++) {
                int c0 = 8 * j + 2 * tid4;
                if (c0     > r0)     sc[j][0] = -1e30f;
                if (c0 + 1 > r0)     sc[j][1] = -1e30f;
                if (c0     > r0 + 8) sc[j][2] = -1e30f;
                if (c0 + 1 > r0 + 8) sc[j][3] = -1e30f;
            }
        }

        // ---- online softmax (two rows per thread) ----
        float mx0 = -1e30f, mx1 = -1e30f;
#pragma unroll
        for (int j = 0; j < 8; j++) {
            mx0 = fmaxf(mx0, fmaxf(sc[j][0], sc[j][1]));
            mx1 = fmaxf(mx1, fmaxf(sc[j][2], sc[j][3]));
        }
        mx0 = fmaxf(mx0, __shfl_xor_sync(FULL, mx0, 1));
        mx0 = fmaxf(mx0, __shfl_xor_sync(FULL, mx0, 2));
        mx1 = fmaxf(mx1, __shfl_xor_sync(FULL, mx1, 1));
        mx1 = fmaxf(mx1, __shfl_xor_sync(FULL, mx1, 2));
        float mn0 = fmaxf(m0, mx0), mn1 = fmaxf(m1, mx1);
        float sum0 = 0.f, sum1 = 0.f;
#pragma unroll
        for (int j = 0; j < 8; j++) {
            sc[j][0] = __expf(sc[j][0] - mn0);
            sc[j][1] = __expf(sc[j][1] - mn0);
            sc[j][2] = __expf(sc[j][2] - mn1);
            sc[j][3] = __expf(sc[j][3] - mn1);
            sum0 += sc[j][0] + sc[j][1];
            sum1 += sc[j][2] + sc[j][3];
        }
        sum0 += __shfl_xor_sync(FULL, sum0, 1);
        sum0 += __shfl_xor_sync(FULL, sum0, 2);
        sum1 += __shfl_xor_sync(FULL, sum1, 1);
        sum1 += __shfl_xor_sync(FULL, sum1, 2);
        float c0 = __expf(m0 - mn0), c1 = __expf(m1 - mn1);
        l0 = l0 * c0 + sum0;
        l1 = l1 * c1 + sum1;
        m0 = mn0; m1 = mn1;
#pragma unroll
        for (int j = 0; j < 8; j++) {
            o[j][0] *= c0; o[j][1] *= c0;
            o[j][2] *= c1; o[j][3] *= c1;
        }

        // ---- stage P (tf32) through the consumed K buffer ----
        __syncthreads();               // all warps done reading Kb
        {
            int pr0 = (16 * warp + gid) * KSTR;
            int pr1 = pr0 + 8 * KSTR;
#pragma unroll
            for (int j = 0; j < 8; j++) {
                int cI = 8 * j + 2 * tid4;
                Kb[pr0 + cI]     = tf32r(sc[j][0]);
                Kb[pr0 + cI + 1] = tf32r(sc[j][1]);
                Kb[pr1 + cI]     = tf32r(sc[j][2]);
                Kb[pr1 + cI + 1] = tf32r(sc[j][3]);
            }
        }
        __syncwarp();                  // P rows are warp-private

        // ---- O += P V ----
#pragma unroll
        for (int k = 0; k < 8; k++) {
            uint32_t pa[4];
            int pb = (16 * warp + gid) * KSTR + 8 * k;
            pa[0] = __float_as_uint(Kb[pb + tid4]);
            pa[1] = __float_as_uint(Kb[pb + 8 * KSTR + tid4]);
            pa[2] = __float_as_uint(Kb[pb + tid4 + 4]);
            pa[3] = __float_as_uint(Kb[pb + 8 * KSTR + tid4 + 4]);
            uint32_t vb2[8][2];
#pragma unroll
            for (int j = 0; j < 8; j++) {
                vb2[j][0] = __float_as_uint(Vb[(8 * k + tid4) * VSTR + 8 * j + gid]);
                vb2[j][1] = __float_as_uint(Vb[(8 * k + tid4 + 4) * VSTR + 8 * j + gid]);
            }
#pragma unroll
            for (int j = 0; j < 8; j++)
                mma_tf32(o[j], pa, vb2[j]);
        }
    }

    // ---- epilogue: normalize, tf32-round, write concat layout ----
    float inv0 = 1.f / l0, inv1 = 1.f / l1;
    int r0 = t0 + 16 * warp + gid;
#pragma unroll
    for (int j = 0; j < 8; j++) {
        int cI = h * 64 + 8 * j + 2 * tid4;
        float2 v0 = make_float2(tf32r(o[j][0] * inv0), tf32r(o[j][1] * inv0));
        float2 v1 = make_float2(tf32r(o[j][2] * inv1), tf32r(o[j][3] * inv1));
        *(float2*)&outp[(size_t)(b * Tt + r0) * Cc + cI]     = v0;
        *(float2*)&outp[(size_t)(b * Tt + r0 + 8) * Cc + cI] = v1;
    }
}

// ---------------------------------------------------------------------------
// Launch
// ---------------------------------------------------------------------------
extern "C" void kernel_launch(void* const* d_in, const int* in_sizes, int n_in,
                              void* d_out, int out_size) {
    const float* x      = (const float*)d_in[0];
    const float* Wq     = (const float*)d_in[1];
    const float* Wk     = (const float*)d_in[2];
    const float* Wv     = (const float*)d_in[3];
    const float* Wo     = (const float*)d_in[4];
    const float* bo     = (const float*)d_in[5];
    const float* W1     = (const float*)d_in[6];
    const float* b1     = (const float*)d_in[7];
    const float* W2     = (const float*)d_in[8];
    const float* b2     = (const float*)d_in[9];
    const float* gamma1 = (const float*)d_in[10];
    const float* beta1  = (const float*)d_in[11];
    const float* gamma2 = (const float*)d_in[12];
    const float* beta2  = (const float*)d_in[13];
    float* out = (float*)d_out;

    float *p_x1, *p_qkv, *p_attn, *p_y, *p_x2, *p_h, *p_wqkv, *p_wo, *p_w1, *p_w2;
    cudaGetSymbolAddress((void**)&p_x1,   g_x1);
    cudaGetSymbolAddress((void**)&p_qkv,  g_qkv);
    cudaGetSymbolAddress((void**)&p_attn, g_attn);
    cudaGetSymbolAddress((void**)&p_y,    g_y);
    cudaGetSymbolAddress((void**)&p_x2,   g_x2);
    cudaGetSymbolAddress((void**)&p_h,    g_h);
    cudaGetSymbolAddress((void**)&p_wqkv, g_wqkv);
    cudaGetSymbolAddress((void**)&p_wo,   g_wo);
    cudaGetSymbolAddress((void**)&p_w1,   g_w1);
    cudaGetSymbolAddress((void**)&p_w2,   g_w2);

    // 0) pack + round weights
    pack_qkv_kernel<<<(Cc * QKV_N + 255) / 256, 256>>>(Wq, Wk, Wv);
    round_kernel<<<(Cc * Cc + 255) / 256, 256>>>(Wo, p_wo, Cc * Cc);
    round_kernel<<<(Cc * FFN_N + 255) / 256, 256>>>(W1, p_w1, Cc * FFN_N);
    round_kernel<<<(FFN_N * Cc + 255) / 256, 256>>>(W2, p_w2, FFN_N * Cc);

    // 1) LN1
    {
        dim3 grid(Cc / 32, Bb), block(32, 8);
        ln_axis1_kernel<<<grid, block>>>(x, gamma1, beta1, p_x1);
    }

    // 2) fused QKV GEMM (tf32-rounded output: feeds tensor-core attention)
    {
        dim3 grid(QKV_N / 128, Mrows / 128);
        gemm_tf32_kernel<false, false, false, true><<<grid, 256>>>(
            p_x1, p_wqkv, nullptr, nullptr, p_qkv, Mrows, QKV_N, Cc);
    }

    // 3) causal flash attention (tf32 tensor cores)
    {
        cudaFuncSetAttribute(attn_mma_kernel,
                             cudaFuncAttributeMaxDynamicSharedMemorySize, ATT_SMEM);
        dim3 grid(Tt / 64, Hh, Bb);
        attn_mma_kernel<<<grid, 128, ATT_SMEM>>>(p_qkv, p_attn);
    }

    // 4) output projection + bias + residual
    {
        dim3 grid(Cc / 128, Mrows / 128);
        gemm_tf32_kernel<true, false, true, false><<<grid, 256>>>(
            p_attn, p_wo, bo, x, p_y, Mrows, Cc, Cc);
    }

    // 5) LN2
    {
        dim3 grid(Cc / 32, Bb), block(32, 8);
        ln_axis1_kernel<<<grid, block>>>(p_y, gamma2, beta2, p_x2);
    }

    // 6) FFN1
    {
        dim3 grid(FFN_N / 128, Mrows / 128);
        gemm_tf32_kernel<true, true, false, true><<<grid, 256>>>(
            p_x2, p_w1, b1, nullptr, p_h, Mrows, FFN_N, Cc);
    }

    // 7) FFN2
    {
        dim3 grid(Cc / 128, Mrows / 128);
        gemm_tf32_kernel<true, false, true, false><<<grid, 256>>>(
            p_h, p_w2, b2, p_y, out, Mrows, Cc, FFN_N);
    }
}